// round 3
// baseline (speedup 1.0000x reference)
#include <cuda_runtime.h>
#include <math.h>

// B=1024, T=128, H1=50 (G1=200), H2=150 (G2=600), D2=100
#define B_SZ 1024
#define T_SZ 128

// output: concat of flattened (waveform_feat[1024,20], pef_logits[1024,2],
//                              feat[1024,30], logits[1024,4])
#define OFF_WF   0
#define OFF_PL   20480
#define OFF_FEAT 22528
#define OFF_LG   53248

static __device__ float g_out1[(size_t)B_SZ * T_SZ * 100];   // layer1 output (52 MB)
static __device__ float g_xg2 [(size_t)B_SZ * T_SZ * 600];   // layer2 fwd input proj (315 MB)
static __device__ float g_W2k [152 * 600];                   // layer2 fwd Whh, k-major, padded
static __device__ float g_net [(size_t)B_SZ * 300];          // out2[:, -1]

__device__ __forceinline__ float sigm (float x) { return 1.f / (1.f + __expf(-x)); }
__device__ __forceinline__ float tanh_(float x) { return 2.f / (1.f + __expf(-2.f * x)) - 1.f; }
__device__ __forceinline__ float lrelu(float x) { return x > 0.f ? x : 0.3f * x; }

// ---------------------------------------------------------------------------
// prep: transpose l2_Whh_f (600x150) -> g_W2k[k][600], rows 150..151 zero
// ---------------------------------------------------------------------------
__global__ void prep_kernel(const float* __restrict__ Whh2f)
{
    int i = blockIdx.x * 256 + threadIdx.x;
    if (i < 152 * 600) {
        int k = i / 600, r = i - k * 600;
        g_W2k[i] = (k < 150) ? Whh2f[r * 150 + k] : 0.f;
    }
}

// ---------------------------------------------------------------------------
// lstm1: grid (64, 2) = (batch groups of 16, direction), 256 threads.
// Threads 0..199 own one gate row each; Whh row register-resident.
// ---------------------------------------------------------------------------
__global__ __launch_bounds__(256) void lstm1_kernel(
    const float* __restrict__ x,
    const float* __restrict__ Wih_f, const float* __restrict__ Whh_f, const float* __restrict__ b_f,
    const float* __restrict__ Wih_b, const float* __restrict__ Whh_b, const float* __restrict__ b_b)
{
    __shared__ __align__(16) float h_s[16 * 52];
    __shared__ float c_s[16 * 50];
    __shared__ float gates_s[16 * 200];
    __shared__ float x_s[16 * 128];

    const int tid = threadIdx.x;
    const int dir = blockIdx.y;
    const int b0  = blockIdx.x * 16;

    const float* Wih = dir ? Wih_b : Wih_f;
    const float* Whh = dir ? Whh_b : Whh_f;
    const float* bb  = dir ? b_b   : b_f;

    for (int i = tid; i < 16 * 128; i += 256) {
        int b = i >> 7, t = i & 127;
        x_s[i] = x[(size_t)(b0 + b) * 128 + t];
    }
    for (int i = tid; i < 16 * 52; i += 256) h_s[i] = 0.f;
    for (int i = tid; i < 16 * 50; i += 256) c_s[i] = 0.f;

    float w[52];
    float wih = 0.f, bv = 0.f;
    if (tid < 200) {
#pragma unroll
        for (int k = 0; k < 52; k++) w[k] = (k < 50) ? Whh[tid * 50 + k] : 0.f;
        wih = Wih[tid];
        bv  = bb[tid];
    }
    __syncthreads();

    for (int s = 0; s < T_SZ; s++) {
        const int t = dir ? (127 - s) : s;
        if (tid < 200) {
#pragma unroll 2
            for (int b = 0; b < 16; b++) {
                float a0 = fmaf(x_s[b * 128 + t], wih, bv);
                float a1 = 0.f, a2 = 0.f, a3 = 0.f;
#pragma unroll
                for (int k4 = 0; k4 < 13; k4++) {
                    float4 h4 = *(const float4*)(h_s + b * 52 + k4 * 4);
                    a0 = fmaf(h4.x, w[k4 * 4 + 0], a0);
                    a1 = fmaf(h4.y, w[k4 * 4 + 1], a1);
                    a2 = fmaf(h4.z, w[k4 * 4 + 2], a2);
                    a3 = fmaf(h4.w, w[k4 * 4 + 3], a3);
                }
                gates_s[b * 200 + tid] = (a0 + a1) + (a2 + a3);
            }
        }
        __syncthreads();
        for (int p = tid; p < 16 * 50; p += 256) {
            int b = p / 50, j = p - b * 50;
            float gi = gates_s[b * 200 + j];
            float gf = gates_s[b * 200 + 50 + j];
            float gg = gates_s[b * 200 + 100 + j];
            float go = gates_s[b * 200 + 150 + j];
            float c = sigm(gf) * c_s[b * 50 + j] + sigm(gi) * tanh_(gg);
            c_s[b * 50 + j] = c;
            float h = sigm(go) * tanh_(c);
            h_s[b * 52 + j] = h;
            g_out1[(size_t)(b0 + b) * 12800 + (size_t)t * 100 + dir * 50 + j] = h;
        }
        __syncthreads();
    }
}

// ---------------------------------------------------------------------------
// xg2 GEMM: C[m][g] = out1[m][:100] . Wih2_f[g][:100] + b2_f[g]
// M = 131072, K = 100, N = 600.  BM=64, BN=64, 256 threads, 4x4 microtiles.
// ---------------------------------------------------------------------------
__global__ __launch_bounds__(256) void xg2_kernel(
    const float* __restrict__ W, const float* __restrict__ bias)
{
    __shared__ __align__(16) float A_s[50 * 68];
    __shared__ __align__(16) float B_s[50 * 68];

    const int m0 = blockIdx.x * 64;
    const int n0 = blockIdx.y * 64;
    const int tid = threadIdx.x;
    const int tx = tid & 15;   // n
    const int ty = tid >> 4;   // m

    float4 acc[4];
#pragma unroll
    for (int i = 0; i < 4; i++) acc[i] = make_float4(0.f, 0.f, 0.f, 0.f);

    for (int ks = 0; ks < 2; ks++) {
        for (int i = tid; i < 3200; i += 256) {
            int mm = i / 50, kk = i - mm * 50;
            A_s[kk * 68 + mm] = g_out1[(size_t)(m0 + mm) * 100 + ks * 50 + kk];
        }
        for (int i = tid; i < 3200; i += 256) {
            int nn = i / 50, kk = i - nn * 50;
            int g = n0 + nn;
            B_s[kk * 68 + nn] = (g < 600) ? W[g * 100 + ks * 50 + kk] : 0.f;
        }
        __syncthreads();
#pragma unroll 10
        for (int k = 0; k < 50; k++) {
            float4 a  = *(const float4*)(A_s + k * 68 + ty * 4);
            float4 bv = *(const float4*)(B_s + k * 68 + tx * 4);
            acc[0].x = fmaf(a.x, bv.x, acc[0].x); acc[0].y = fmaf(a.x, bv.y, acc[0].y);
            acc[0].z = fmaf(a.x, bv.z, acc[0].z); acc[0].w = fmaf(a.x, bv.w, acc[0].w);
            acc[1].x = fmaf(a.y, bv.x, acc[1].x); acc[1].y = fmaf(a.y, bv.y, acc[1].y);
            acc[1].z = fmaf(a.y, bv.z, acc[1].z); acc[1].w = fmaf(a.y, bv.w, acc[1].w);
            acc[2].x = fmaf(a.z, bv.x, acc[2].x); acc[2].y = fmaf(a.z, bv.y, acc[2].y);
            acc[2].z = fmaf(a.z, bv.z, acc[2].z); acc[2].w = fmaf(a.z, bv.w, acc[2].w);
            acc[3].x = fmaf(a.w, bv.x, acc[3].x); acc[3].y = fmaf(a.w, bv.y, acc[3].y);
            acc[3].z = fmaf(a.w, bv.z, acc[3].z); acc[3].w = fmaf(a.w, bv.w, acc[3].w);
        }
        __syncthreads();
    }

    const int nbase = n0 + tx * 4;
    if (nbase < 600) {
        float4 bb = *(const float4*)(bias + nbase);
#pragma unroll
        for (int mi = 0; mi < 4; mi++) {
            float4 o = acc[mi];
            o.x += bb.x; o.y += bb.y; o.z += bb.z; o.w += bb.w;
            *(float4*)(g_xg2 + (size_t)(m0 + ty * 4 + mi) * 600 + nbase) = o;
        }
    }
}

// ---------------------------------------------------------------------------
// lstm2 forward recurrence. Grid 128 CTAs x 8 batches, 640 threads.
// Threads 0..599 own gate row r. Whh k-major: k<76 slab in smem, rest from L2.
// Final h -> g_net[b][0:150].
// ---------------------------------------------------------------------------
extern __shared__ float lstm2_sm[];

__global__ __launch_bounds__(640, 1) void lstm2_kernel()
{
    float* Wlo   = lstm2_sm;               // 76*600 = 45600 floats
    float* gates = lstm2_sm + 45600;       // 8*608  = 4864 floats
    float* h_s   = gates + 4864;           // 8*152  = 1216 floats

    const int tid = threadIdx.x;
    const int b0  = blockIdx.x * 8;
    const int r   = tid;

    for (int i = tid; i < 45600; i += 640) Wlo[i] = g_W2k[i];
    for (int i = tid; i < 8 * 152; i += 640) h_s[i] = 0.f;

    // update-phase slot assignment (fixed per thread); c persists in registers
    const int pa = tid;                 // slots 0..639
    const int ba = pa / 150, ja = pa - ba * 150;
    const int pb = tid + 640;           // slots 640..1199 (tid < 560)
    const int bb2 = pb / 150, jb = pb - bb2 * 150;
    const bool has_b = (tid < 560);
    float ca = 0.f, cb = 0.f;

    const float* xbase = g_xg2 + (size_t)b0 * 76800 + r;   // + b*76800 + t*600
    const float* Whi   = g_W2k + r;                        // + k*600
    __syncthreads();

    for (int t = 0; t < T_SZ; t++) {
        if (tid < 600) {
            float acc[8];
#pragma unroll
            for (int b = 0; b < 8; b++)
                acc[b] = __ldg(xbase + (size_t)b * 76800 + t * 600);

#pragma unroll
            for (int k4 = 0; k4 < 38; k4++) {
                const int k = k4 * 4;
                float w0, w1, w2, w3;
                if (k4 < 19) {
                    w0 = Wlo[(k + 0) * 600 + r];
                    w1 = Wlo[(k + 1) * 600 + r];
                    w2 = Wlo[(k + 2) * 600 + r];
                    w3 = Wlo[(k + 3) * 600 + r];
                } else {
                    w0 = __ldg(Whi + (k + 0) * 600);
                    w1 = __ldg(Whi + (k + 1) * 600);
                    w2 = __ldg(Whi + (k + 2) * 600);
                    w3 = __ldg(Whi + (k + 3) * 600);
                }
                float4 hv[8];
#pragma unroll
                for (int b = 0; b < 8; b++)
                    hv[b] = *(const float4*)(h_s + b * 152 + k);
#pragma unroll
                for (int b = 0; b < 8; b++) {
                    acc[b] = fmaf(hv[b].x, w0, acc[b]);
                    acc[b] = fmaf(hv[b].y, w1, acc[b]);
                    acc[b] = fmaf(hv[b].z, w2, acc[b]);
                    acc[b] = fmaf(hv[b].w, w3, acc[b]);
                }
            }
#pragma unroll
            for (int b = 0; b < 8; b++) gates[b * 608 + r] = acc[b];
        }
        __syncthreads();

        {
            float gi = gates[ba * 608 + ja];
            float gf = gates[ba * 608 + 150 + ja];
            float gg = gates[ba * 608 + 300 + ja];
            float go = gates[ba * 608 + 450 + ja];
            ca = sigm(gf) * ca + sigm(gi) * tanh_(gg);
            float h = sigm(go) * tanh_(ca);
            h_s[ba * 152 + ja] = h;
            if (t == 127) g_net[(size_t)(b0 + ba) * 300 + ja] = h;
        }
        if (has_b) {
            float gi = gates[bb2 * 608 + jb];
            float gf = gates[bb2 * 608 + 150 + jb];
            float gg = gates[bb2 * 608 + 300 + jb];
            float go = gates[bb2 * 608 + 450 + jb];
            cb = sigm(gf) * cb + sigm(gi) * tanh_(gg);
            float h = sigm(go) * tanh_(cb);
            h_s[bb2 * 152 + jb] = h;
            if (t == 127) g_net[(size_t)(b0 + bb2) * 300 + jb] = h;
        }
        __syncthreads();
    }
}

// ---------------------------------------------------------------------------
// bwd2: layer2 backward needs only its first step (t = T-1, h0 = c0 = 0).
// Grid 256 CTAs x 4 batches, 256 threads. Writes g_net[b][150:300].
// ---------------------------------------------------------------------------
__global__ __launch_bounds__(256) void bwd2_kernel(
    const float* __restrict__ Wih2b, const float* __restrict__ b2b)
{
    __shared__ float xv[4 * 100];
    __shared__ float gsm[4 * 600];
    const int tid = threadIdx.x;
    const int b0  = blockIdx.x * 4;

    for (int i = tid; i < 400; i += 256) {
        int b = i / 100, c = i - b * 100;
        xv[i] = g_out1[(size_t)(b0 + b) * 12800 + 127 * 100 + c];
    }
    __syncthreads();

    for (int p = tid; p < 2400; p += 256) {
        int b = p / 600, rr = p - b * 600;
        float acc = b2b[rr];
        const float* Wr = Wih2b + rr * 100;
        const float* xr = xv + b * 100;
#pragma unroll 4
        for (int k = 0; k < 100; k++) acc = fmaf(Wr[k], xr[k], acc);
        gsm[b * 600 + rr] = acc;
    }
    __syncthreads();

    for (int p = tid; p < 600; p += 256) {
        int b = p / 150, j = p - b * 150;
        float gi = gsm[b * 600 + j];
        float gg = gsm[b * 600 + 300 + j];
        float go = gsm[b * 600 + 450 + j];
        float c = sigm(gi) * tanh_(gg);           // c0 = 0 -> forget term vanishes
        float h = sigm(go) * tanh_(c);
        g_net[(size_t)(b0 + b) * 300 + 150 + j] = h;
    }
}

// ---------------------------------------------------------------------------
// heads: one 32-thread block per batch.
// ---------------------------------------------------------------------------
__global__ __launch_bounds__(32) void heads_kernel(
    const float* __restrict__ rrs,
    const float* __restrict__ head_W, const float* __restrict__ head_b,
    const float* __restrict__ pef1_W, const float* __restrict__ pef1_b,
    const float* __restrict__ pef2_W, const float* __restrict__ pef2_b,
    const float* __restrict__ fc_W,   const float* __restrict__ fc_b,
    float* __restrict__ out)
{
    __shared__ float net_s[300];
    __shared__ float feat_s[30];
    __shared__ float rrs_s[4];
    const int b = blockIdx.x;
    const int tid = threadIdx.x;

    for (int i = tid; i < 300; i += 32) net_s[i] = g_net[(size_t)b * 300 + i];
    if (tid < 4) rrs_s[tid] = rrs[b * 4 + tid];
    __syncthreads();

    if (tid < 20) {
        float acc = head_b[tid];
        const float* Wr = head_W + tid * 300;
        for (int k = 0; k < 300; k++) acc = fmaf(Wr[k], net_s[k], acc);
        float v = lrelu(acc);
        feat_s[tid] = v;
        out[OFF_WF + b * 20 + tid] = v;
    } else if (tid < 30) {
        int j = tid - 20;
        float acc = pef1_b[j];
#pragma unroll
        for (int k = 0; k < 4; k++) acc = fmaf(pef1_W[j * 4 + k], rrs_s[k], acc);
        feat_s[20 + j] = lrelu(acc);
    }
    __syncthreads();

    if (tid < 2) {
        float acc = pef2_b[tid];
#pragma unroll
        for (int k = 0; k < 10; k++) acc = fmaf(pef2_W[tid * 10 + k], feat_s[20 + k], acc);
        out[OFF_PL + b * 2 + tid] = acc;
    } else if (tid < 6) {
        int j = tid - 2;
        float acc = fc_b[j];
#pragma unroll
        for (int k = 0; k < 30; k++) acc = fmaf(fc_W[j * 30 + k], feat_s[k], acc);
        out[OFF_LG + b * 4 + j] = acc;
    }
    if (tid < 30) out[OFF_FEAT + b * 30 + tid] = feat_s[tid];
}

// ---------------------------------------------------------------------------
extern "C" void kernel_launch(void* const* d_in, const int* in_sizes, int n_in,
                              void* d_out, int out_size)
{
    const float* x        = (const float*)d_in[0];
    const float* rrs      = (const float*)d_in[1];
    const float* l1_Wih_f = (const float*)d_in[2];
    const float* l1_Whh_f = (const float*)d_in[3];
    const float* l1_b_f   = (const float*)d_in[4];
    const float* l1_Wih_b = (const float*)d_in[5];
    const float* l1_Whh_b = (const float*)d_in[6];
    const float* l1_b_b   = (const float*)d_in[7];
    const float* l2_Wih_f = (const float*)d_in[8];
    const float* l2_Whh_f = (const float*)d_in[9];
    const float* l2_b_f   = (const float*)d_in[10];
    const float* l2_Wih_b = (const float*)d_in[11];
    /* d_in[12] = l2_Whh_b unused (single backward step from h0=0) */
    const float* l2_b_b   = (const float*)d_in[13];
    const float* head_W   = (const float*)d_in[14];
    const float* head_b   = (const float*)d_in[15];
    const float* pef1_W   = (const float*)d_in[16];
    const float* pef1_b   = (const float*)d_in[17];
    const float* pef2_W   = (const float*)d_in[18];
    const float* pef2_b   = (const float*)d_in[19];
    const float* fc_W     = (const float*)d_in[20];
    const float* fc_b     = (const float*)d_in[21];
    float* out = (float*)d_out;

    (void)cudaFuncSetAttribute(lstm2_kernel,
                               cudaFuncAttributeMaxDynamicSharedMemorySize, 206720);

    prep_kernel<<<(152 * 600 + 255) / 256, 256>>>(l2_Whh_f);
    lstm1_kernel<<<dim3(64, 2), 256>>>(x, l1_Wih_f, l1_Whh_f, l1_b_f,
                                          l1_Wih_b, l1_Whh_b, l1_b_b);
    xg2_kernel<<<dim3(2048, 10), 256>>>(l2_Wih_f, l2_b_f);
    lstm2_kernel<<<128, 640, 206720>>>();
    bwd2_kernel<<<256, 256>>>(l2_Wih_b, l2_b_b);
    heads_kernel<<<1024, 32>>>(rrs, head_W, head_b, pef1_W, pef1_b,
                               pef2_W, pef2_b, fc_W, fc_b, out);
}